// round 4
// baseline (speedup 1.0000x reference)
#include <cuda_runtime.h>
#include <cuda_bf16.h>
#include <cstdint>

// ---------------------------------------------------------------------------
// Problem constants
// ---------------------------------------------------------------------------
#define BATCH   2048
#define IN_DIM  768
#define HID_DIM 24576
#define TOPK    50

// ---------------------------------------------------------------------------
// Device scratch (allocation-free contract: __device__ globals)
// ---------------------------------------------------------------------------
__device__ float g_scratch_pre [ (size_t)BATCH * HID_DIM ];   // pre_acts fallback
__device__ float g_scratch_code[ (size_t)BATCH * HID_DIM ];   // sparse_code fallback
__device__ float g_scratch_tv  [ BATCH * TOPK ];
__device__ float g_scratch_ti  [ BATCH * TOPK ];
__device__ float g_wdecT       [ (size_t)HID_DIM * IN_DIM ];  // W_dec transposed
__device__ float g_tk_vals     [ BATCH * TOPK ];              // for decode
__device__ int   g_tk_idx      [ BATCH * TOPK ];

// ---------------------------------------------------------------------------
// Encoder GEMM: pre[b,h] = sum_i (x[b,i]-pre_bias[i]) * W_enc[h,i] + latent_bias[h]
// fp32, 128x128 tile, BK=8, 8x8 per thread, smem double buffered.
// Dims divide evenly (2048/128, 24576/128, 768/8) -> no bounds checks.
// Grid mapping: blockIdx.x = batch tile (fast), blockIdx.y = hidden tile, so
// concurrent CTAs share W_enc tiles via L2 (x is 6 MB, fully L2-resident).
// ---------------------------------------------------------------------------
#define GB_M 128
#define GB_N 128
#define GB_K 8

__global__ __launch_bounds__(256) void encode_gemm_kernel(
    const float* __restrict__ x,
    const float* __restrict__ W,          // [HID_DIM, IN_DIM] row-major
    const float* __restrict__ pre_bias,   // [IN_DIM]
    const float* __restrict__ lat_bias,   // [HID_DIM]
    float* __restrict__ out)              // [BATCH, HID_DIM]
{
    __shared__ float As[2][GB_K][GB_M];
    __shared__ float Bs[2][GB_K][GB_N];

    const int tid  = threadIdx.x;
    const int bm   = blockIdx.x * GB_M;   // batch offset  (fast grid dim)
    const int bn   = blockIdx.y * GB_N;   // hidden offset (slow grid dim)
    const int lrow = tid >> 1;            // 0..127
    const int lcol = (tid & 1) * 4;       // 0 or 4
    const int tx   = tid & 15;
    const int ty   = tid >> 4;

    const float* Aptr = x + (size_t)(bm + lrow) * IN_DIM;
    const float* Bptr = W + (size_t)(bn + lrow) * IN_DIM;

    // --- preload tile 0 ---
    {
        float4 a4  = *(const float4*)(Aptr + lcol);
        float4 pb4 = *(const float4*)(pre_bias + lcol);
        float4 b4  = *(const float4*)(Bptr + lcol);
        As[0][lcol + 0][lrow] = a4.x - pb4.x;
        As[0][lcol + 1][lrow] = a4.y - pb4.y;
        As[0][lcol + 2][lrow] = a4.z - pb4.z;
        As[0][lcol + 3][lrow] = a4.w - pb4.w;
        Bs[0][lcol + 0][lrow] = b4.x;
        Bs[0][lcol + 1][lrow] = b4.y;
        Bs[0][lcol + 2][lrow] = b4.z;
        Bs[0][lcol + 3][lrow] = b4.w;
    }
    __syncthreads();

    float acc[8][8];
#pragma unroll
    for (int i = 0; i < 8; ++i)
#pragma unroll
        for (int j = 0; j < 8; ++j) acc[i][j] = 0.f;

    const int NIT = IN_DIM / GB_K;  // 96
    for (int t = 0; t < NIT; ++t) {
        const int buf = t & 1;
        float4 na, nb, npb;
        if (t + 1 < NIT) {
            const int k0 = (t + 1) * GB_K;
            na  = *(const float4*)(Aptr + k0 + lcol);
            npb = *(const float4*)(pre_bias + k0 + lcol);
            nb  = *(const float4*)(Bptr + k0 + lcol);
        }
#pragma unroll
        for (int kk = 0; kk < GB_K; ++kk) {
            float a[8], b[8];
            *(float4*)(a)     = *(const float4*)&As[buf][kk][ty * 8];
            *(float4*)(a + 4) = *(const float4*)&As[buf][kk][ty * 8 + 4];
            *(float4*)(b)     = *(const float4*)&Bs[buf][kk][tx * 8];
            *(float4*)(b + 4) = *(const float4*)&Bs[buf][kk][tx * 8 + 4];
#pragma unroll
            for (int i = 0; i < 8; ++i)
#pragma unroll
                for (int j = 0; j < 8; ++j)
                    acc[i][j] = fmaf(a[i], b[j], acc[i][j]);
        }
        if (t + 1 < NIT) {
            const int nbuf = buf ^ 1;
            As[nbuf][lcol + 0][lrow] = na.x - npb.x;
            As[nbuf][lcol + 1][lrow] = na.y - npb.y;
            As[nbuf][lcol + 2][lrow] = na.z - npb.z;
            As[nbuf][lcol + 3][lrow] = na.w - npb.w;
            Bs[nbuf][lcol + 0][lrow] = nb.x;
            Bs[nbuf][lcol + 1][lrow] = nb.y;
            Bs[nbuf][lcol + 2][lrow] = nb.z;
            Bs[nbuf][lcol + 3][lrow] = nb.w;
        }
        __syncthreads();
    }

    // epilogue: + latent_bias, float4 stores
    float lb[8];
    *(float4*)(lb)     = *(const float4*)(lat_bias + bn + tx * 8);
    *(float4*)(lb + 4) = *(const float4*)(lat_bias + bn + tx * 8 + 4);
#pragma unroll
    for (int i = 0; i < 8; ++i) {
        float* op = out + (size_t)(bm + ty * 8 + i) * HID_DIM + bn + tx * 8;
        float4 v0, v1;
        v0.x = acc[i][0] + lb[0]; v0.y = acc[i][1] + lb[1];
        v0.z = acc[i][2] + lb[2]; v0.w = acc[i][3] + lb[3];
        v1.x = acc[i][4] + lb[4]; v1.y = acc[i][5] + lb[5];
        v1.z = acc[i][6] + lb[6]; v1.w = acc[i][7] + lb[7];
        *(float4*)(op)     = v0;
        *(float4*)(op + 4) = v1;
    }
}

// ---------------------------------------------------------------------------
// Zero-fill (for sparse_code)
// ---------------------------------------------------------------------------
__global__ void zero_f4_kernel(float4* __restrict__ p, size_t n4)
{
    size_t i = (size_t)blockIdx.x * blockDim.x + threadIdx.x;
    size_t stride = (size_t)gridDim.x * blockDim.x;
    float4 z = {0.f, 0.f, 0.f, 0.f};
    for (; i < n4; i += stride) p[i] = z;
}

// ---------------------------------------------------------------------------
// W_dec transpose: [IN_DIM, HID_DIM] -> [HID_DIM, IN_DIM]
// ---------------------------------------------------------------------------
__global__ void transpose_wdec_kernel(const float* __restrict__ Wd,
                                      float* __restrict__ WdT)
{
    __shared__ float tile[32][33];
    const int cx = blockIdx.x * 32 + threadIdx.x;   // hidden col in Wd
    const int ry = blockIdx.y * 32 + threadIdx.y;   // input row in Wd
#pragma unroll
    for (int j = 0; j < 32; j += 8)
        tile[threadIdx.y + j][threadIdx.x] = Wd[(size_t)(ry + j) * HID_DIM + cx];
    __syncthreads();
    const int ox = blockIdx.y * 32 + threadIdx.x;   // input col in WdT
    const int oy = blockIdx.x * 32 + threadIdx.y;   // hidden row in WdT
#pragma unroll
    for (int j = 0; j < 32; j += 8)
        WdT[(size_t)(oy + j) * IN_DIM + ox] = tile[threadIdx.x][threadIdx.y + j];
}

// ---------------------------------------------------------------------------
// Top-K per row. Exact fp32, jax.lax.top_k semantics (descending values,
// ties -> lowest index first). Radix-bucket threshold (top 11 bits of the
// positive-float bit pattern, which is order-preserving) then exact selection
// over a small candidate set with composite key (value_bits desc, index asc).
// Also scatters into sparse_code (pre-zeroed) and fills decode-side arrays.
// ---------------------------------------------------------------------------
#define TK_THREADS 256
#define CAND_CAP   4096

__global__ __launch_bounds__(TK_THREADS) void topk_kernel(
    const float* __restrict__ pre,
    float* __restrict__ code,
    float* __restrict__ tv_out, float* __restrict__ ti_out,
    float* __restrict__ dvals, int* __restrict__ didx)
{
    __shared__ unsigned hist[2048];
    __shared__ unsigned long long cand[CAND_CAP];
    __shared__ unsigned chunkS[32];
    __shared__ int s_bstar;
    __shared__ int s_m;

    const int r   = blockIdx.x;
    const int tid = threadIdx.x;
    const float* row = pre + (size_t)r * HID_DIM;

    for (int i = tid; i < 2048; i += TK_THREADS) hist[i] = 0u;
    if (tid == 0) s_m = 0;
    __syncthreads();

    // pass 1: histogram over top-11 bits (positive float bits < 0x80000000)
    for (int h = tid; h < HID_DIM; h += TK_THREADS) {
        float v = row[h];
        unsigned key = (v > 0.f) ? __float_as_uint(v) : 0u;
        atomicAdd(&hist[key >> 20], 1u);
    }
    __syncthreads();

    if (tid < 32) {
        unsigned s = 0;
#pragma unroll
        for (int b = 0; b < 64; ++b) s += hist[tid * 64 + b];
        chunkS[tid] = s;
    }
    __syncthreads();

    if (tid == 0) {
        unsigned cum = 0;
        int c = 31;
        for (; c > 0; --c) {
            if (cum + chunkS[c] >= TOPK) break;
            cum += chunkS[c];
        }
        int b = c * 64 + 63;
        for (; b > c * 64; --b) {
            if (cum + hist[b] >= TOPK) break;
            cum += hist[b];
        }
        s_bstar = b;
    }
    __syncthreads();
    const int bstar = s_bstar;

    // pass 2: gather candidates (count >= TOPK by construction)
    for (int h = tid; h < HID_DIM; h += TK_THREADS) {
        float v = row[h];
        unsigned key = (v > 0.f) ? __float_as_uint(v) : 0u;
        if ((int)(key >> 20) >= bstar) {
            int p = atomicAdd(&s_m, 1);
            if (p < CAND_CAP)
                cand[p] = ((unsigned long long)key << 32) | (unsigned)(~(unsigned)h);
        }
    }
    __syncthreads();
    const int M = (s_m < CAND_CAP) ? s_m : CAND_CAP;

    // warp-0 selection sort over the small candidate set
    if (tid < 32) {
        for (int j = 0; j < TOPK; ++j) {
            unsigned long long best = 0ull;
            for (int p = tid; p < M; p += 32) {
                unsigned long long c = cand[p];
                if (c > best) best = c;
            }
#pragma unroll
            for (int off = 16; off; off >>= 1) {
                unsigned long long o = __shfl_xor_sync(0xffffffffu, best, off);
                if (o > best) best = o;
            }
            for (int p = tid; p < M; p += 32)
                if (cand[p] == best) cand[p] = 0ull;
            if (tid == 0) {
                unsigned key = (unsigned)(best >> 32);
                unsigned h   = ~((unsigned)best);
                float val = __uint_as_float(key);
                tv_out[r * TOPK + j] = val;
                ti_out[r * TOPK + j] = (float)h;
                dvals[r * TOPK + j]  = val;
                didx[r * TOPK + j]   = (int)h;
                code[(size_t)r * HID_DIM + h] = val;
            }
            __syncwarp();
        }
    }
}

// ---------------------------------------------------------------------------
// Decode: recon[b,i] = pre_bias[i] + sum_k vals[b,k] * WdT[idx[b,k], i]
// ---------------------------------------------------------------------------
__global__ __launch_bounds__(256) void decode_kernel(
    const float* __restrict__ vals, const int* __restrict__ idx,
    const float* __restrict__ WdT, const float* __restrict__ pre_bias,
    float* __restrict__ recon)
{
    __shared__ float sv[TOPK];
    __shared__ int   si[TOPK];
    const int r = blockIdx.x;
    if (threadIdx.x < TOPK) {
        sv[threadIdx.x] = vals[r * TOPK + threadIdx.x];
        si[threadIdx.x] = idx[r * TOPK + threadIdx.x];
    }
    __syncthreads();
#pragma unroll
    for (int ii = 0; ii < IN_DIM / 256; ++ii) {
        const int i = threadIdx.x + ii * 256;
        float acc = pre_bias[i];
#pragma unroll 10
        for (int k = 0; k < TOPK; ++k)
            acc = fmaf(sv[k], WdT[(size_t)si[k] * IN_DIM + i], acc);
        recon[(size_t)r * IN_DIM + i] = acc;
    }
}

// ---------------------------------------------------------------------------
// Launch
// ---------------------------------------------------------------------------
extern "C" void kernel_launch(void* const* d_in, const int* in_sizes, int n_in,
                              void* d_out, int out_size)
{
    const float* x        = (const float*)d_in[0];
    const float* W_enc    = (const float*)d_in[1];
    const float* W_dec    = (const float*)d_in[2];
    const float* pre_bias = (const float*)d_in[3];
    const float* lat_bias = (const float*)d_in[4];
    float* out = (float*)d_out;

    const long long nR = (long long)BATCH * IN_DIM;     // 1,572,864
    const long long nC = (long long)BATCH * HID_DIM;    // 50,331,648
    const long long nV = (long long)BATCH * TOPK;       // 102,400

    float *s_pre, *s_code, *s_tv, *s_ti, *wdecT, *tkv;
    int* tki;
    cudaGetSymbolAddress((void**)&s_pre,  g_scratch_pre);
    cudaGetSymbolAddress((void**)&s_code, g_scratch_code);
    cudaGetSymbolAddress((void**)&s_tv,   g_scratch_tv);
    cudaGetSymbolAddress((void**)&s_ti,   g_scratch_ti);
    cudaGetSymbolAddress((void**)&wdecT,  g_wdecT);
    cudaGetSymbolAddress((void**)&tkv,    g_tk_vals);
    cudaGetSymbolAddress((void**)&tki,    g_tk_idx);

    // Output layout: (reconstruction, sparse_code, pre_acts, topk_values, topk_indices)
    float *recon, *code, *pre, *tv, *ti;
    if ((long long)out_size >= nR + nC + nC + nV + nV) {
        recon = out;
        code  = out + nR;
        pre   = code + nC;
        tv    = pre + nC;
        ti    = tv + nV;
    } else {
        recon = out;
        code  = s_code;
        pre   = s_pre;
        tv    = s_tv;
        ti    = s_ti;
    }

    // 1. encoder GEMM (fp32 exact -> top-k set identical to reference)
    {
        dim3 grid(BATCH / GB_M, HID_DIM / GB_N);  // (16, 192) batch-fast for L2 W reuse
        encode_gemm_kernel<<<grid, 256>>>(x, W_enc, pre_bias, lat_bias, pre);
    }

    // 2. zero sparse_code
    zero_f4_kernel<<<2048, 256>>>((float4*)code, (size_t)nC / 4);

    // 3. transpose W_dec (independent of 1-2)
    {
        dim3 grid(HID_DIM / 32, IN_DIM / 32);     // (768, 24)
        dim3 block(32, 8);
        transpose_wdec_kernel<<<grid, block>>>(W_dec, wdecT);
    }

    // 4. top-k + scatter
    topk_kernel<<<BATCH, TK_THREADS>>>(pre, code, tv, ti, tkv, tki);

    // 5. sparse decode
    decode_kernel<<<BATCH, 256>>>(tkv, tki, wdecT, pre_bias, recon);
}

// round 12
// speedup vs baseline: 1.1270x; 1.1270x over previous
#include <cuda_runtime.h>
#include <cstdint>

// ---------------------------------------------------------------------------
// Problem constants
// ---------------------------------------------------------------------------
#define BATCH   2048
#define IN_DIM  768
#define HID_DIM 24576
#define TOPK    50
#define NSEL    64          // approx candidates kept for exact re-rank
#define RR_ROWS 16          // candidate rows per re-rank round
#define RR_STRIDE (IN_DIM + 4)   // 772 floats: 16B-aligned rows, 2-way LDS conflict

// ---------------------------------------------------------------------------
// Device scratch (allocation-free contract: __device__ globals)
// ---------------------------------------------------------------------------
__device__ float g_scratch_pre [ (size_t)BATCH * HID_DIM ];
__device__ float g_scratch_code[ (size_t)BATCH * HID_DIM ];
__device__ float g_scratch_tv  [ BATCH * TOPK ];
__device__ float g_scratch_ti  [ BATCH * TOPK ];
__device__ float g_wdecT       [ (size_t)HID_DIM * IN_DIM ];
__device__ float g_tk_vals     [ BATCH * TOPK ];
__device__ int   g_tk_idx      [ BATCH * TOPK ];

// ===========================================================================
// Encoder GEMM: 3xTF32 emulation on legacy tensor cores (mma.sync.m16n8k8).
//   pre[b,h] = (x[b,:]-pre_bias) . W[h,:] + latent_bias[h]
// Residual error ~2^-22 relative; top-k boundary decisions are made by the
// reference-order serial-fma re-rank in topk_kernel.
// CTA tile 128(M) x 256(N), BK=32, 8 warps of 64x64, double-buffered smem.
// ===========================================================================
#define CM 128
#define CN 256
#define CK 32
#define NCH (IN_DIM / CK)        // 24
#define APAD 36
#define ASZ (CM * APAD)
#define BSZ (CN * APAD)
#define STG (ASZ + BSZ)
#define GEMM_SMEM (2 * STG * 4)  // 110592 bytes

__device__ __forceinline__ void split2(float v, uint32_t& hi, uint32_t& lo) {
    asm("cvt.rna.tf32.f32 %0, %1;" : "=r"(hi) : "f"(v));
    float l = v - __uint_as_float(hi);
    asm("cvt.rna.tf32.f32 %0, %1;" : "=r"(lo) : "f"(l));
}

__device__ __forceinline__ void mma8(float* c, const uint32_t* a, const uint32_t* b) {
    asm volatile(
        "mma.sync.aligned.m16n8k8.row.col.f32.tf32.tf32.f32 "
        "{%0,%1,%2,%3}, {%4,%5,%6,%7}, {%8,%9}, {%0,%1,%2,%3};"
        : "+f"(c[0]), "+f"(c[1]), "+f"(c[2]), "+f"(c[3])
        : "r"(a[0]), "r"(a[1]), "r"(a[2]), "r"(a[3]), "r"(b[0]), "r"(b[1]));
}

__global__ __launch_bounds__(256, 1) void encode_gemm_mma(
    const float* __restrict__ x,
    const float* __restrict__ W,          // [HID_DIM, IN_DIM]
    const float* __restrict__ pre_bias,
    const float* __restrict__ lat_bias,
    float* __restrict__ out)              // [BATCH, HID_DIM]
{
    extern __shared__ float sm[];
    const int tid  = threadIdx.x;
    const int wid  = tid >> 5;
    const int lane = tid & 31;
    const int g    = lane >> 2;
    const int t    = lane & 3;

    const int bm = blockIdx.x * CM;
    const int bn = blockIdx.y * CN;

    const int m_off = (wid & 1) * 64;
    const int n_off = (wid >> 1) * 64;

    float acc[4][8][4];
#pragma unroll
    for (int i = 0; i < 4; ++i)
#pragma unroll
        for (int j = 0; j < 8; ++j)
#pragma unroll
            for (int k = 0; k < 4; ++k) acc[i][j][k] = 0.f;

    float4 av[4], bv[8];

#pragma unroll
    for (int i = 0; i < 4; ++i) {
        int idx = tid + i * 256;
        av[i] = *(const float4*)(x + (size_t)(bm + (idx >> 3)) * IN_DIM + (idx & 7) * 4);
    }
#pragma unroll
    for (int i = 0; i < 8; ++i) {
        int idx = tid + i * 256;
        bv[i] = *(const float4*)(W + (size_t)(bn + (idx >> 3)) * IN_DIM + (idx & 7) * 4);
    }
#pragma unroll
    for (int i = 0; i < 4; ++i) {
        int idx = tid + i * 256;
        int c4 = (idx & 7) * 4;
        float4 pb = *(const float4*)(pre_bias + c4);
        float4 v = av[i];
        v.x -= pb.x; v.y -= pb.y; v.z -= pb.z; v.w -= pb.w;
        *(float4*)(sm + (idx >> 3) * APAD + c4) = v;
    }
#pragma unroll
    for (int i = 0; i < 8; ++i) {
        int idx = tid + i * 256;
        *(float4*)(sm + ASZ + (idx >> 3) * APAD + (idx & 7) * 4) = bv[i];
    }
    __syncthreads();

    for (int c = 0; c < NCH; ++c) {
        const int buf = c & 1;
        const bool more = (c + 1 < NCH);

        if (more) {
            const int k0 = (c + 1) * CK;
#pragma unroll
            for (int i = 0; i < 4; ++i) {
                int idx = tid + i * 256;
                av[i] = *(const float4*)(x + (size_t)(bm + (idx >> 3)) * IN_DIM + k0 + (idx & 7) * 4);
            }
#pragma unroll
            for (int i = 0; i < 8; ++i) {
                int idx = tid + i * 256;
                bv[i] = *(const float4*)(W + (size_t)(bn + (idx >> 3)) * IN_DIM + k0 + (idx & 7) * 4);
            }
        }

        const float* Ab = sm + buf * STG;
        const float* Bb = Ab + ASZ;
#pragma unroll
        for (int k8 = 0; k8 < 4; ++k8) {
            const int kb = k8 * 8;
            uint32_t bh[16], bl[16];
#pragma unroll
            for (int nt = 0; nt < 8; ++nt) {
                int rn = (n_off + nt * 8 + g) * APAD + kb + t;
                split2(Bb[rn],     bh[nt * 2],     bl[nt * 2]);
                split2(Bb[rn + 4], bh[nt * 2 + 1], bl[nt * 2 + 1]);
            }
#pragma unroll
            for (int mt = 0; mt < 4; ++mt) {
                int r0 = (m_off + mt * 16 + g) * APAD + kb + t;
                int r1 = r0 + 8 * APAD;
                uint32_t ah[4], al[4];
                split2(Ab[r0],     ah[0], al[0]);
                split2(Ab[r1],     ah[1], al[1]);
                split2(Ab[r0 + 4], ah[2], al[2]);
                split2(Ab[r1 + 4], ah[3], al[3]);
#pragma unroll
                for (int nt = 0; nt < 8; ++nt) {
                    mma8(acc[mt][nt], ah, &bh[nt * 2]);   // hi*hi
                    mma8(acc[mt][nt], ah, &bl[nt * 2]);   // hi*lo
                    mma8(acc[mt][nt], al, &bh[nt * 2]);   // lo*hi
                }
            }
        }

        if (more) {
            float* dst = sm + (buf ^ 1) * STG;
            const int k0 = (c + 1) * CK;
#pragma unroll
            for (int i = 0; i < 4; ++i) {
                int idx = tid + i * 256;
                int c4 = (idx & 7) * 4;
                float4 pb = *(const float4*)(pre_bias + k0 + c4);
                float4 v = av[i];
                v.x -= pb.x; v.y -= pb.y; v.z -= pb.z; v.w -= pb.w;
                *(float4*)(dst + (idx >> 3) * APAD + c4) = v;
            }
#pragma unroll
            for (int i = 0; i < 8; ++i) {
                int idx = tid + i * 256;
                *(float4*)(dst + ASZ + (idx >> 3) * APAD + (idx & 7) * 4) = bv[i];
            }
            __syncthreads();
        }
    }

#pragma unroll
    for (int mt = 0; mt < 4; ++mt) {
        const int grow = bm + m_off + mt * 16 + g;
#pragma unroll
        for (int nt = 0; nt < 8; ++nt) {
            const int h = bn + n_off + nt * 8 + 2 * t;
            float2 lb = *(const float2*)(lat_bias + h);
            float2 v0, v1;
            v0.x = acc[mt][nt][0] + lb.x;
            v0.y = acc[mt][nt][1] + lb.y;
            v1.x = acc[mt][nt][2] + lb.x;
            v1.y = acc[mt][nt][3] + lb.y;
            *(float2*)(out + (size_t)grow * HID_DIM + h)       = v0;
            *(float2*)(out + (size_t)(grow + 8) * HID_DIM + h) = v1;
        }
    }
}

// ---------------------------------------------------------------------------
// Zero-fill (for sparse_code)
// ---------------------------------------------------------------------------
__global__ void zero_f4_kernel(float4* __restrict__ p, size_t n4)
{
    size_t i = (size_t)blockIdx.x * blockDim.x + threadIdx.x;
    size_t stride = (size_t)gridDim.x * blockDim.x;
    float4 z = {0.f, 0.f, 0.f, 0.f};
    for (; i < n4; i += stride) p[i] = z;
}

// ---------------------------------------------------------------------------
// W_dec transpose: [IN_DIM, HID_DIM] -> [HID_DIM, IN_DIM]
// ---------------------------------------------------------------------------
__global__ void transpose_wdec_kernel(const float* __restrict__ Wd,
                                      float* __restrict__ WdT)
{
    __shared__ float tile[32][33];
    const int cx = blockIdx.x * 32 + threadIdx.x;
    const int ry = blockIdx.y * 32 + threadIdx.y;
#pragma unroll
    for (int j = 0; j < 32; j += 8)
        tile[threadIdx.y + j][threadIdx.x] = Wd[(size_t)(ry + j) * HID_DIM + cx];
    __syncthreads();
    const int ox = blockIdx.y * 32 + threadIdx.x;
    const int oy = blockIdx.x * 32 + threadIdx.y;
#pragma unroll
    for (int j = 0; j < 32; j += 8)
        WdT[(size_t)(oy + j) * IN_DIM + ox] = tile[threadIdx.x][threadIdx.y + j];
}

// ---------------------------------------------------------------------------
// Top-K per row with REFERENCE-ORDER exact re-rank:
//   1) radix-bucket + approx selection keeps top NSEL=64 candidates
//   2) for each candidate, ONE thread recomputes the dot product with a
//      strictly serial fmaf chain over k=0..767 (identical accumulation
//      order to the R4 fp32 GEMM that matched the reference ordering),
//      + latent_bias, then relu
//   3) final top-50 ranked by these values (desc, index asc)
// Dynamic smem: xs | hist | big (cand ring reused as W row staging buffer).
// ---------------------------------------------------------------------------
#define TK_THREADS 512
#define CAND_CAP   4096
#define TK_XS_OFF   0
#define TK_HIST_OFF (IN_DIM * 4)                        // 3072
#define TK_BIG_OFF  (TK_HIST_OFF + 2048 * 4)            // 11264
#define TK_BIG_SZ   (RR_ROWS * RR_STRIDE * 4)           // 49408 >= CAND_CAP*8? no: 32768 < 49408 ok
#define TK_SMEM     (TK_BIG_OFF + TK_BIG_SZ)            // 60672 bytes

__global__ __launch_bounds__(TK_THREADS) void topk_kernel(
    const float* __restrict__ pre,
    const float* __restrict__ x,
    const float* __restrict__ W,          // [HID_DIM, IN_DIM]
    const float* __restrict__ pre_bias,
    const float* __restrict__ lat_bias,
    float* __restrict__ code,
    float* __restrict__ tv_out, float* __restrict__ ti_out,
    float* __restrict__ dvals, int* __restrict__ didx)
{
    extern __shared__ char dsm[];
    float*    xs   = (float*)(dsm + TK_XS_OFF);
    unsigned* hist = (unsigned*)(dsm + TK_HIST_OFF);
    unsigned long long* cand = (unsigned long long*)(dsm + TK_BIG_OFF);
    float*    wbuf = (float*)(dsm + TK_BIG_OFF);        // reuses cand region

    __shared__ int   sel_idx[NSEL];
    __shared__ float sel_val[NSEL];
    __shared__ unsigned long long skey[NSEL];
    __shared__ unsigned chunkS[32];
    __shared__ int s_bstar;
    __shared__ int s_m;

    const int r   = blockIdx.x;
    const int tid = threadIdx.x;
    const float* row = pre + (size_t)r * HID_DIM;

    // x row (bias-subtracted, same op as GEMM A-prep) into smem
    for (int i = tid; i < IN_DIM; i += TK_THREADS)
        xs[i] = x[(size_t)r * IN_DIM + i] - pre_bias[i];

    for (int i = tid; i < 2048; i += TK_THREADS) hist[i] = 0u;
    if (tid == 0) s_m = 0;
    __syncthreads();

    // pass 1: histogram over top-11 bits of positive-float pattern
    for (int h = tid; h < HID_DIM; h += TK_THREADS) {
        float v = row[h];
        unsigned key = (v > 0.f) ? __float_as_uint(v) : 0u;
        atomicAdd(&hist[key >> 20], 1u);
    }
    __syncthreads();

    if (tid < 32) {
        unsigned s = 0;
#pragma unroll
        for (int b = 0; b < 64; ++b) s += hist[tid * 64 + b];
        chunkS[tid] = s;
    }
    __syncthreads();

    if (tid == 0) {
        unsigned cum = 0;
        int c = 31;
        for (; c > 0; --c) {
            if (cum + chunkS[c] >= NSEL) break;
            cum += chunkS[c];
        }
        int b = c * 64 + 63;
        for (; b > c * 64; --b) {
            if (cum + hist[b] >= NSEL) break;
            cum += hist[b];
        }
        s_bstar = b;
    }
    __syncthreads();
    const int bstar = s_bstar;

    // pass 2: gather candidates (count >= NSEL by construction)
    for (int h = tid; h < HID_DIM; h += TK_THREADS) {
        float v = row[h];
        unsigned key = (v > 0.f) ? __float_as_uint(v) : 0u;
        if ((int)(key >> 20) >= bstar) {
            int p = atomicAdd(&s_m, 1);
            if (p < CAND_CAP)
                cand[p] = ((unsigned long long)key << 32) | (unsigned)(~(unsigned)h);
        }
    }
    __syncthreads();
    const int M = (s_m < CAND_CAP) ? s_m : CAND_CAP;

    // warp-0: approx top-NSEL selection (descending composite key)
    if (tid < 32) {
        const int nsel = (M < NSEL) ? M : NSEL;
        for (int j = 0; j < NSEL; ++j) {
            if (j >= nsel) { if (tid == 0) sel_idx[j] = -1; continue; }
            unsigned long long best = 0ull;
            for (int p = tid; p < M; p += 32) {
                unsigned long long c = cand[p];
                if (c > best) best = c;
            }
#pragma unroll
            for (int off = 16; off; off >>= 1) {
                unsigned long long o = __shfl_xor_sync(0xffffffffu, best, off);
                if (o > best) best = o;
            }
            for (int p = tid; p < M; p += 32)
                if (cand[p] == best) cand[p] = 0ull;
            if (tid == 0) sel_idx[j] = (int)(~((unsigned)best));
            __syncwarp();
        }
    }
    __syncthreads();   // cand region is dead; wbuf may overwrite it now

    // exact re-rank: 4 rounds of 16 rows; serial fmaf chain per candidate
    for (int round = 0; round < NSEL / RR_ROWS; ++round) {
        // cooperative coalesced load of 16 W rows into wbuf
#pragma unroll
        for (int i = 0; i < (RR_ROWS * IN_DIM / 4) / TK_THREADS; ++i) {   // 6
            int idx  = tid + i * TK_THREADS;
            int rrow = idx / (IN_DIM / 4);
            int c4   = idx % (IN_DIM / 4);
            int h    = sel_idx[round * RR_ROWS + rrow];
            float4 v = make_float4(0.f, 0.f, 0.f, 0.f);
            if (h >= 0)
                v = *(const float4*)(W + (size_t)h * IN_DIM + c4 * 4);
            *(float4*)(wbuf + rrow * RR_STRIDE + c4 * 4) = v;
        }
        __syncthreads();

        if (tid < RR_ROWS) {
            const int ci = round * RR_ROWS + tid;
            const int h  = sel_idx[ci];
            const float* wr = wbuf + tid * RR_STRIDE;
            float acc = 0.f;
            // strictly serial, increasing k — reference accumulation order
            for (int k = 0; k < IN_DIM; ++k)
                acc = fmaf(xs[k], wr[k], acc);
            float v = (h >= 0) ? fmaxf(acc + lat_bias[h], 0.f) : 0.f;
            sel_val[ci] = v;
        }
        __syncthreads();
    }

    // build exact composite keys (value bits desc, index asc via ~h)
    if (tid < NSEL) {
        int h = sel_idx[tid];
        unsigned kb = (h >= 0) ? __float_as_uint(sel_val[tid]) : 0u;
        skey[tid] = ((unsigned long long)kb << 32) |
                    (unsigned)(~(unsigned)((h >= 0) ? h : 0x7FFFFFFF));
    }
    __syncthreads();

    // warp-0: exact top-50 selection + outputs
    if (tid < 32) {
        for (int j = 0; j < TOPK; ++j) {
            unsigned long long best = 0ull;
#pragma unroll
            for (int p = tid; p < NSEL; p += 32) {
                unsigned long long c = skey[p];
                if (c > best) best = c;
            }
#pragma unroll
            for (int off = 16; off; off >>= 1) {
                unsigned long long o = __shfl_xor_sync(0xffffffffu, best, off);
                if (o > best) best = o;
            }
#pragma unroll
            for (int p = tid; p < NSEL; p += 32)
                if (skey[p] == best) skey[p] = 0ull;
            if (tid == 0) {
                unsigned key = (unsigned)(best >> 32);
                unsigned h   = ~((unsigned)best);
                float val = __uint_as_float(key);
                tv_out[r * TOPK + j] = val;
                ti_out[r * TOPK + j] = (float)h;
                dvals[r * TOPK + j]  = val;
                didx[r * TOPK + j]   = (int)h;
                code[(size_t)r * HID_DIM + h] = val;
            }
            __syncwarp();
        }
    }
}

// ---------------------------------------------------------------------------
// Decode: recon[b,i] = pre_bias[i] + sum_k vals[b,k] * WdT[idx[b,k], i]
// ---------------------------------------------------------------------------
__global__ __launch_bounds__(256) void decode_kernel(
    const float* __restrict__ vals, const int* __restrict__ idx,
    const float* __restrict__ WdT, const float* __restrict__ pre_bias,
    float* __restrict__ recon)
{
    __shared__ float sv[TOPK];
    __shared__ int   si[TOPK];
    const int r = blockIdx.x;
    if (threadIdx.x < TOPK) {
        sv[threadIdx.x] = vals[r * TOPK + threadIdx.x];
        si[threadIdx.x] = idx[r * TOPK + threadIdx.x];
    }
    __syncthreads();
#pragma unroll
    for (int ii = 0; ii < IN_DIM / 256; ++ii) {
        const int i = threadIdx.x + ii * 256;
        float acc = pre_bias[i];
#pragma unroll 10
        for (int k = 0; k < TOPK; ++k)
            acc = fmaf(sv[k], WdT[(size_t)si[k] * IN_DIM + i], acc);
        recon[(size_t)r * IN_DIM + i] = acc;
    }
}

// ---------------------------------------------------------------------------
// Launch
// ---------------------------------------------------------------------------
extern "C" void kernel_launch(void* const* d_in, const int* in_sizes, int n_in,
                              void* d_out, int out_size)
{
    const float* x        = (const float*)d_in[0];
    const float* W_enc    = (const float*)d_in[1];
    const float* W_dec    = (const float*)d_in[2];
    const float* pre_bias = (const float*)d_in[3];
    const float* lat_bias = (const float*)d_in[4];
    float* out = (float*)d_out;

    const long long nR = (long long)BATCH * IN_DIM;
    const long long nC = (long long)BATCH * HID_DIM;
    const long long nV = (long long)BATCH * TOPK;

    float *s_pre, *s_code, *s_tv, *s_ti, *wdecT, *tkv;
    int* tki;
    cudaGetSymbolAddress((void**)&s_pre,  g_scratch_pre);
    cudaGetSymbolAddress((void**)&s_code, g_scratch_code);
    cudaGetSymbolAddress((void**)&s_tv,   g_scratch_tv);
    cudaGetSymbolAddress((void**)&s_ti,   g_scratch_ti);
    cudaGetSymbolAddress((void**)&wdecT,  g_wdecT);
    cudaGetSymbolAddress((void**)&tkv,    g_tk_vals);
    cudaGetSymbolAddress((void**)&tki,    g_tk_idx);

    // Output layout: (reconstruction, sparse_code, pre_acts, topk_values, topk_indices)
    float *recon, *code, *pre, *tv, *ti;
    if ((long long)out_size >= nR + nC + nC + nV + nV) {
        recon = out;
        code  = out + nR;
        pre   = code + nC;
        tv    = pre + nC;
        ti    = tv + nV;
    } else {
        recon = out;
        code  = s_code;
        pre   = s_pre;
        tv    = s_tv;
        ti    = s_ti;
    }

    // 1. encoder GEMM (3xTF32 on legacy mma.sync tensor cores)
    cudaFuncSetAttribute(encode_gemm_mma,
                         cudaFuncAttributeMaxDynamicSharedMemorySize, GEMM_SMEM);
    {
        dim3 grid(BATCH / CM, HID_DIM / CN);   // (16, 96), batch-fast for L2 W reuse
        encode_gemm_mma<<<grid, 256, GEMM_SMEM>>>(x, W_enc, pre_bias, lat_bias, pre);
    }

    // 2. zero sparse_code
    zero_f4_kernel<<<2048, 256>>>((float4*)code, (size_t)nC / 4);

    // 3. transpose W_dec
    {
        dim3 grid(HID_DIM / 32, IN_DIM / 32);
        dim3 block(32, 8);
        transpose_wdec_kernel<<<grid, block>>>(W_dec, wdecT);
    }

    // 4. top-k (approx select -> reference-order exact re-rank) + scatter
    cudaFuncSetAttribute(topk_kernel,
                         cudaFuncAttributeMaxDynamicSharedMemorySize, TK_SMEM);
    topk_kernel<<<BATCH, TK_THREADS, TK_SMEM>>>(pre, x, W_enc, pre_bias, lat_bias,
                                                code, tv, ti, tkv, tki);

    // 5. sparse decode
    decode_kernel<<<BATCH, 256>>>(tkv, tki, wdecT, pre_bias, recon);
}